// round 12
// baseline (speedup 1.0000x reference)
#include <cuda_runtime.h>
#include <cuda_bf16.h>
#include <cstdint>

// ---------------- problem constants ----------------
#define BS   32
#define C    64
#define H    96
#define W    96
#define HW   (H*W)
#define CHW  ((size_t)C*HW)
#define TT   64
#define HID  128
#define EPS  1e-5f

// conv tiling: CTA = 4 rows x 32 cols = 128 px (M), 64 oc (N), K = 9*64
#define NTX 3
#define NTY 24
#define NT  (NTX*NTY)        // 72 tiles/image

// halo tile: 6 rows x 34 cols = 204 pixel-rows, each 64 bf16 = 128B
#define TPX 204
#define OFF_TH 0
#define CONV_SMEM 27648      // tile only -> 6 CTAs/SM

#define TAILB_SMEM_FLOATS (2048+4096+2048+160)
#define TAILB_SMEM_BYTES  (TAILB_SMEM_FLOATS*4)

// B fragment table: [s(9)][kc(4)][nh(2)][f(2)][lane(32)] uint4
#define NFRAG 4608

// ---------------- device scratch ----------------
__device__ uint32_t g_f1[BS*HW*32];   // conv1 out, pixel-major bf16 (2 ch per u32)
__device__ uint4    g_bfrag1[NFRAG];  // conv1 weight MMA fragments (72KB)
__device__ uint4    g_bfrag2[NFRAG];
__device__ float    g_bias1[C];
__device__ float    g_bias2[C];
__device__ float    g_part[BS*NT*C];
__device__ float    g_logits[BS*TT];

// ---------------- helpers ----------------
static __device__ __forceinline__ uint32_t smem_u32(const void* p) {
    uint32_t a;
    asm("{ .reg .u64 t; cvta.to.shared.u64 t, %1; cvt.u32.u64 %0, t; }" : "=r"(a) : "l"(p));
    return a;
}
static __device__ __forceinline__ void ldsm4(uint32_t* r, uint32_t a) {
    asm volatile("ldmatrix.sync.aligned.m8n8.x4.shared.b16 {%0,%1,%2,%3}, [%4];"
        : "=r"(r[0]), "=r"(r[1]), "=r"(r[2]), "=r"(r[3]) : "r"(a));
}
static __device__ __forceinline__ void mma16816(float* c, const uint32_t* a, uint32_t b0, uint32_t b1) {
    asm volatile("mma.sync.aligned.m16n8k16.row.col.f32.bf16.bf16.f32 "
        "{%0,%1,%2,%3}, {%4,%5,%6,%7}, {%8,%9}, {%0,%1,%2,%3};"
        : "+f"(c[0]), "+f"(c[1]), "+f"(c[2]), "+f"(c[3])
        : "r"(a[0]), "r"(a[1]), "r"(a[2]), "r"(a[3]), "r"(b0), "r"(b1));
}
static __device__ __forceinline__ void cp16(uint32_t dst, const void* src) {
    asm volatile("cp.async.cg.shared.global [%0], [%1], 16;" :: "r"(dst), "l"(src));
}
static __device__ __forceinline__ void cp_commit() {
    asm volatile("cp.async.commit_group;" ::: "memory");
}
static __device__ __forceinline__ void cp_wait0() {
    asm volatile("cp.async.wait_group 0;" ::: "memory");
}
static __device__ __forceinline__ uint32_t packbf(float a, float b) {
    __nv_bfloat162 v;
    v.x = __float2bfloat16(a);
    v.y = __float2bfloat16(b);
    return *(uint32_t*)&v;
}

// ---------------- prep: fold BN + build B MMA fragment tables ----------
// Entry (cv, s, kc, nh, f, lane): the uint4 that ldmatrix.x4 would have
// delivered to this lane for B matrices {oc0..7,k0..7 / k8..15 / oc8..15 x ...}
__global__ void prep_kernel(const float* __restrict__ w1, const float* __restrict__ g1,
                            const float* __restrict__ b1, const float* __restrict__ m1,
                            const float* __restrict__ v1,
                            const float* __restrict__ w2, const float* __restrict__ g2,
                            const float* __restrict__ b2, const float* __restrict__ m2,
                            const float* __restrict__ v2) {
    int idx = blockIdx.x*256 + threadIdx.x;
    if (idx < 2*NFRAG) {
        int cv = idx / NFRAG;
        int r  = idx - cv*NFRAG;
        int l  = r & 31;
        int f  = (r >> 5) & 1;
        int nh = (r >> 6) & 1;
        int kc = (r >> 7) & 3;
        int s  = r >> 9;
        const float* w = cv ? w2 : w1;
        const float* g = cv ? g2 : g1;
        const float* v = cv ? v2 : v1;
        int o  = nh*32 + f*16 + (l >> 2);
        int kb = kc*16 + ((l & 3) << 1);
        float sc0 = g[o]   * rsqrtf(v[o]   + EPS);
        float sc8 = g[o+8] * rsqrtf(v[o+8] + EPS);
        // folded weight W[oc][ic] for slice s: w[(oc*64+ic)*9+s]*scale[oc]
        const float* w0 = w + ((size_t)o*64)*9 + s;
        const float* w8 = w + ((size_t)(o+8)*64)*9 + s;
        uint4 e;
        e.x = packbf(w0[(size_t)(kb  )*9]*sc0, w0[(size_t)(kb+1)*9]*sc0);
        e.y = packbf(w0[(size_t)(kb+8)*9]*sc0, w0[(size_t)(kb+9)*9]*sc0);
        e.z = packbf(w8[(size_t)(kb  )*9]*sc8, w8[(size_t)(kb+1)*9]*sc8);
        e.w = packbf(w8[(size_t)(kb+8)*9]*sc8, w8[(size_t)(kb+9)*9]*sc8);
        (cv ? g_bfrag2 : g_bfrag1)[r] = e;
    }
    if (idx < C) {
        g_bias1[idx] = b1[idx] - m1[idx]*g1[idx]*rsqrtf(v1[idx] + EPS);
        g_bias2[idx] = b2[idx] - m2[idx]*g2[idx]*rsqrtf(v2[idx] + EPS);
    }
}

// ---------------- HMMA conv: bf16 implicit GEMM, B from gmem fragments -
// STORE=1: reads x (fp32 NCHW, fused transpose+cvt), writes g_f1
// STORE=0: reads g_f1 (bf16 pixel-major, cp.async fill), writes pooled partials
template<int STORE>
__launch_bounds__(256, 6)
__global__ void conv_mma(const float* __restrict__ xin) {
    extern __shared__ uint8_t sm[];
    const uint32_t sb = smem_u32(sm);

    const int tid  = threadIdx.x;
    const int lane = tid & 31;
    const int wrp  = tid >> 5;
    const int x0 = blockIdx.x * 32, y0 = blockIdx.y * 4;
    const int b  = blockIdx.z;

    const float* bias = STORE ? g_bias1 : g_bias2;

    // fill halo tile (bf16, swizzled rows of 128B)
    if (STORE) {
        // fused transpose: read NCHW fp32, convert, store [px][ch] swizzled
        const float* inb = xin + (size_t)b * CHW;
        for (int i = tid; i < TPX*8; i += 256) {
            int ch8 = i / TPX, pxl = i - ch8*TPX;
            int rr = pxl / 34, cc = pxl - rr*34;
            int py = y0 + rr - 1, px = x0 + cc - 1;
            uint4 v = make_uint4(0,0,0,0);
            if (py >= 0 && py < H && px >= 0 && px < W) {
                const float* p = inb + (size_t)(ch8*8)*HW + py*W + px;
                v.x = packbf(p[0],    p[HW]);
                v.y = packbf(p[2*HW], p[3*HW]);
                v.z = packbf(p[4*HW], p[5*HW]);
                v.w = packbf(p[6*HW], p[7*HW]);
            }
            uint32_t boff = (uint32_t)pxl*128 + (((uint32_t)ch8*16) ^ (((uint32_t)pxl & 7u) << 4));
            *(uint4*)(sm + OFF_TH + boff) = v;
        }
    } else {
        // cp.async fill: 16B per (pixel, 8-ch group), zero halo via STS
        const uint32_t* f1b = g_f1 + ((size_t)b*HW << 5);
        for (int i = tid; i < TPX*8; i += 256) {
            int pxl = i >> 3, ch8 = i & 7;
            int rr = pxl / 34, cc = pxl - rr*34;
            int py = y0 + rr - 1, px = x0 + cc - 1;
            uint32_t boff = (uint32_t)pxl*128 + (((uint32_t)ch8*16) ^ (((uint32_t)pxl & 7u) << 4));
            if (py >= 0 && py < H && px >= 0 && px < W) {
                cp16(sb + OFF_TH + boff, f1b + ((size_t)(py*W + px) << 5) + ch8*4);
            } else {
                *(uint4*)(sm + OFF_TH + boff) = make_uint4(0,0,0,0);
            }
        }
        cp_commit();
        cp_wait0();
    }
    __syncthreads();      // the ONLY barrier before the epilogue

    // per-lane ldsm address components
    const int g  = lane >> 3, lr = lane & 7;
    const int mb = (wrp & 3) * 32;
    const int nh = wrp >> 2;
    const int nb = nh * 32;
    const uint32_t kaddA = (g >= 2) ? 16u : 0u;
    int pA[2];
    #pragma unroll
    for (int f = 0; f < 2; f++) {
        int p = mb + f*16 + ((g & 1) << 3) + lr;
        pA[f] = (p >> 5)*34 + (p & 31);
    }
    // B fragment pointer (pre-offset by nh, lane)
    const uint4* bfp = (STORE ? g_bfrag1 : g_bfrag2) + nh*64 + lane;

    float acc[2][4][4];
    #pragma unroll
    for (int m = 0; m < 2; m++)
        #pragma unroll
        for (int n = 0; n < 4; n++)
            #pragma unroll
            for (int q = 0; q < 4; q++) acc[m][n][q] = 0.f;

    for (int s = 0; s < 9; s++) {
        const int ky = s / 3, kx = s - 3*(s/3);
        const int soff = ky*34 + kx;
        const uint4* bs = bfp + s*512;

        #pragma unroll
        for (int kc = 0; kc < 4; kc++) {
            uint32_t AH[2][4];
            #pragma unroll
            for (int f = 0; f < 2; f++) {
                uint32_t pxl = (uint32_t)(pA[f] + soff);
                uint32_t aoff = pxl*128 + (((uint32_t)kc*32 + kaddA) ^ ((pxl & 7u) << 4));
                ldsm4(AH[f], sb + OFF_TH + aoff);
            }
            #pragma unroll
            for (int f = 0; f < 2; f++) {
                uint4 rb = __ldg(bs + kc*128 + f*32);
                mma16816(acc[0][2*f],   AH[0], rb.x, rb.y);
                mma16816(acc[0][2*f+1], AH[0], rb.z, rb.w);
                mma16816(acc[1][2*f],   AH[1], rb.x, rb.y);
                mma16816(acc[1][2*f+1], AH[1], rb.z, rb.w);
            }
        }
    }

    // ---------------- epilogue ----------------
    if (STORE) {
        uint32_t* f1b = g_f1 + ((size_t)b*HW << 5);
        #pragma unroll
        for (int m = 0; m < 2; m++) {
            #pragma unroll
            for (int n = 0; n < 4; n++) {
                int oc = nb + n*8 + (lane & 3)*2;
                float b0 = bias[oc], b1v = bias[oc+1];
                #pragma unroll
                for (int hh = 0; hh < 2; hh++) {
                    int p = mb + m*16 + (lane >> 2) + hh*8;
                    int py = y0 + (p >> 5), px = x0 + (p & 31);
                    f1b[((size_t)(py*W + px) << 5) + (oc >> 1)] =
                        packbf(fmaxf(acc[m][n][hh*2]   + b0,  0.f),
                               fmaxf(acc[m][n][hh*2+1] + b1v, 0.f));
                }
            }
        }
    } else {
        float cs[4][2];
        #pragma unroll
        for (int n = 0; n < 4; n++) {
            int oc = nb + n*8 + (lane & 3)*2;
            float b0 = bias[oc], b1v = bias[oc+1];
            float s0 = 0.f, s1 = 0.f;
            #pragma unroll
            for (int m = 0; m < 2; m++) {
                s0 += fmaxf(acc[m][n][0] + b0, 0.f) + fmaxf(acc[m][n][2] + b0, 0.f);
                s1 += fmaxf(acc[m][n][1] + b1v, 0.f) + fmaxf(acc[m][n][3] + b1v, 0.f);
            }
            #pragma unroll
            for (int d = 4; d < 32; d <<= 1) {
                s0 += __shfl_xor_sync(0xffffffffu, s0, d);
                s1 += __shfl_xor_sync(0xffffffffu, s1, d);
            }
            cs[n][0] = s0; cs[n][1] = s1;
        }
        __syncthreads();                       // tile reads done -> reuse as pool
        float* pool = (float*)(sm + OFF_TH);   // [4 mrow][64 oc]
        if (lane < 4) {
            #pragma unroll
            for (int n = 0; n < 4; n++) {
                int oc = nb + n*8 + lane*2;
                pool[(wrp & 3)*64 + oc]     = cs[n][0];
                pool[(wrp & 3)*64 + oc + 1] = cs[n][1];
            }
        }
        __syncthreads();
        if (tid < C) {
            float s = pool[tid] + pool[64 + tid] + pool[128 + tid] + pool[192 + tid];
            int tileIdx = blockIdx.y * NTX + blockIdx.x;
            g_part[((size_t)b*NT + tileIdx)*C + tid] = s;
        }
    }
}

// ---------------- tailA: per-sample pool finish + MLP -> logits --------
__launch_bounds__(512)
__global__ void tailA_kernel(const float* __restrict__ w1, const float* __restrict__ b1,
                             const float* __restrict__ w2, const float* __restrict__ b2) {
    __shared__ float red[512];
    __shared__ float feat[64];
    __shared__ float hidden[128];
    const int tid = threadIdx.x;
    const int b = blockIdx.x;

    {
        int c = tid & 63, grp = tid >> 6;
        float s = 0.f;
        const float* gp = g_part + ((size_t)b*NT + grp*9)*C + c;
        #pragma unroll
        for (int t = 0; t < 9; t++) s += gp[t*C];
        red[tid] = s;
    }
    __syncthreads();
    if (tid < 64) {
        float s = 0.f;
        #pragma unroll
        for (int g2 = 0; g2 < 8; g2++) s += red[g2*64 + tid];
        feat[tid] = s * (1.f/(float)HW);
    }
    __syncthreads();

    {
        int j = tid >> 2, part = tid & 3;
        float h = 0.f;
        #pragma unroll
        for (int ii = 0; ii < 16; ii++) {
            int i = part*16 + ii;
            h += feat[i] * w1[i*HID + j];
        }
        h += __shfl_xor_sync(0xffffffffu, h, 1);
        h += __shfl_xor_sync(0xffffffffu, h, 2);
        if (part == 0) hidden[j] = fmaxf(h + b1[j], 0.f);
    }
    __syncthreads();

    {
        int t = tid >> 3, part = tid & 7;
        float s = 0.f;
        #pragma unroll
        for (int jj = 0; jj < 16; jj++) {
            int j = part*16 + jj;
            s += hidden[j] * w2[j*TT + t];
        }
        s += __shfl_xor_sync(0xffffffffu, s, 1);
        s += __shfl_xor_sync(0xffffffffu, s, 2);
        s += __shfl_xor_sync(0xffffffffu, s, 4);
        if (part == 0) g_logits[b*TT + t] = s + b2[t];
    }
}

// ---------------- tailB: softmax, loss, EMA, outputs -------------------
__launch_bounds__(1024)
__global__ void tailB_kernel(const float* __restrict__ ref_x, const int* __restrict__ ref_types,
                             const float* __restrict__ ref_proj, float* __restrict__ dout) {
    extern __shared__ float smf[];
    float* logit  = smf;             // [32][64] -> becomes type_weights
    float* refnew = logit + 2048;    // [64][64]
    float* refx   = refnew + 4096;   // [32][64]
    float* lossv  = refx + 2048;     // [32]
    float* coeff  = lossv + 32;      // [32]
    float* decay  = coeff + 32;      // [64]
    int*   st     = (int*)(decay + 64);

    const int tid = threadIdx.x;
    const int NTH = 1024;
    if (tid < BS) st[tid] = ref_types[tid];
    for (int i = tid; i < BS*TT; i += NTH) logit[i] = g_logits[i];
    for (int i = tid; i < BS*C; i += NTH) refx[i] = ref_x[i];
    __syncthreads();

    {
        const int wp = tid >> 5, ln = tid & 31;
        float* lr = logit + wp*TT;
        float a = lr[ln], c2 = lr[ln + 32];
        float tgt = lr[st[wp]];
        float mx = fmaxf(a, c2);
        #pragma unroll
        for (int s = 16; s; s >>= 1) mx = fmaxf(mx, __shfl_xor_sync(0xffffffffu, mx, s));
        float ea = expf(a - mx), eb = expf(c2 - mx);
        float sum = ea + eb;
        #pragma unroll
        for (int s = 16; s; s >>= 1) sum += __shfl_xor_sync(0xffffffffu, sum, s);
        if (ln == 0) lossv[wp] = mx + logf(sum) - tgt;
        float inv = 1.f / sum;
        __syncwarp();
        lr[ln]      = ea * inv;
        lr[ln + 32] = eb * inv;
    }
    if (tid < TT) {
        int cnt = 0;
        for (int i = 0; i < BS; i++) cnt += (st[i] == tid);
        float r = 1.f;
        for (int q = 0; q < cnt; q++) r *= 0.99f;
        decay[tid] = r;
    }
    if (tid >= 64 && tid < 96) {
        int i = tid - 64;
        int after = 0;
        for (int j = i + 1; j < BS; j++) after += (st[j] == st[i]);
        float r = 0.01f;
        for (int q = 0; q < after; q++) r *= 0.99f;
        coeff[i] = r;
    }
    __syncthreads();

    for (int idx = tid; idx < TT*C; idx += NTH) {
        int t = idx >> 6, c = idx & 63;
        float v = decay[t] * ref_proj[idx];
        #pragma unroll 8
        for (int i = 0; i < BS; i++)
            if (st[i] == t) v += coeff[i] * refx[i*C + c];
        refnew[idx] = v;
        dout[2049 + idx] = v;
    }
    __syncthreads();

    for (int idx = tid; idx < BS*C; idx += NTH) {
        int bb = idx >> 6, c = idx & 63;
        float s = refx[idx];
        const float* twr = logit + bb*TT;
        #pragma unroll 16
        for (int t = 0; t < TT; t++) s += twr[t] * refnew[t*C + c];
        dout[idx] = s;
    }
    if (tid == 0) {
        float s = 0.f;
        for (int i = 0; i < BS; i++) s += lossv[i];
        dout[2048] = s * (1.f/(float)BS);
    }
}

// ---------------- launch ----------------
extern "C" void kernel_launch(void* const* d_in, const int* in_sizes, int n_in,
                              void* d_out, int out_size) {
    const float* x        = (const float*)d_in[0];
    const float* ref_x    = (const float*)d_in[1];
    const int*   ref_types= (const int*)  d_in[2];
    const float* conv1_w  = (const float*)d_in[3];
    const float* bn1_g    = (const float*)d_in[4];
    const float* bn1_b    = (const float*)d_in[5];
    const float* bn1_m    = (const float*)d_in[6];
    const float* bn1_v    = (const float*)d_in[7];
    const float* conv2_w  = (const float*)d_in[8];
    const float* bn2_g    = (const float*)d_in[9];
    const float* bn2_b    = (const float*)d_in[10];
    const float* bn2_m    = (const float*)d_in[11];
    const float* bn2_v    = (const float*)d_in[12];
    const float* mlp_w1   = (const float*)d_in[13];
    const float* mlp_b1   = (const float*)d_in[14];
    const float* mlp_w2   = (const float*)d_in[15];
    const float* mlp_b2   = (const float*)d_in[16];
    const float* ref_proj = (const float*)d_in[17];
    float* out = (float*)d_out;

    cudaFuncSetAttribute(conv_mma<1>, cudaFuncAttributeMaxDynamicSharedMemorySize, CONV_SMEM);
    cudaFuncSetAttribute(conv_mma<0>, cudaFuncAttributeMaxDynamicSharedMemorySize, CONV_SMEM);
    cudaFuncSetAttribute(tailB_kernel, cudaFuncAttributeMaxDynamicSharedMemorySize, TAILB_SMEM_BYTES);

    prep_kernel<<<36, 256>>>(conv1_w, bn1_g, bn1_b, bn1_m, bn1_v,
                             conv2_w, bn2_g, bn2_b, bn2_m, bn2_v);

    dim3 cgrid(NTX, NTY, BS);
    conv_mma<1><<<cgrid, 256, CONV_SMEM>>>(x);
    conv_mma<0><<<cgrid, 256, CONV_SMEM>>>(x);

    tailA_kernel<<<BS, 512>>>(mlp_w1, mlp_b1, mlp_w2, mlp_b2);
    tailB_kernel<<<1, 1024, TAILB_SMEM_BYTES>>>(ref_x, ref_types, ref_proj, out);
}

// round 13
// speedup vs baseline: 1.8553x; 1.8553x over previous
#include <cuda_runtime.h>
#include <cuda_bf16.h>
#include <cstdint>

// ---------------- problem constants ----------------
#define BS   32
#define C    64
#define H    96
#define W    96
#define HW   (H*W)
#define CHW  ((size_t)C*HW)
#define TT   64
#define HID  128
#define EPS  1e-5f

// conv tiling: CTA = 4 rows x 32 cols = 128 px (M), 64 oc (N), K = 9*64
#define NTX 3
#define NTY 24
#define NT  (NTX*NTY)        // 72 tiles/image

// halo tile: 6 rows x 34 cols = 204 pixel-rows, each 64 bf16 = 128B
#define TPX 204
#define OFF_TH 0
#define OFF_B0 26624
#define OFF_B1 34816
#define CONV_SMEM 43008      // 5 CTAs/SM (215KB < 228KB)

#define TAILB_SMEM_FLOATS (2048+4096+2048+160)
#define TAILB_SMEM_BYTES  (TAILB_SMEM_FLOATS*4)

// ---------------- device scratch ----------------
__device__ uint32_t g_f1[BS*HW*32];   // conv1 out, pixel-major bf16 (2 ch per u32)
__device__ uint32_t g_wbm1[9*2048];   // weights: per slice 8KB bf16, ldsm-swizzled
__device__ uint32_t g_wbm2[9*2048];
__device__ float    g_bias1[C];
__device__ float    g_bias2[C];
__device__ float    g_part[BS*NT*C];
__device__ float    g_logits[BS*TT];

// ---------------- helpers ----------------
static __device__ __forceinline__ uint32_t smem_u32(const void* p) {
    uint32_t a;
    asm("{ .reg .u64 t; cvta.to.shared.u64 t, %1; cvt.u32.u64 %0, t; }" : "=r"(a) : "l"(p));
    return a;
}
static __device__ __forceinline__ void ldsm4(uint32_t* r, uint32_t a) {
    asm volatile("ldmatrix.sync.aligned.m8n8.x4.shared.b16 {%0,%1,%2,%3}, [%4];"
        : "=r"(r[0]), "=r"(r[1]), "=r"(r[2]), "=r"(r[3]) : "r"(a));
}
static __device__ __forceinline__ void mma16816(float* c, const uint32_t* a, uint32_t b0, uint32_t b1) {
    asm volatile("mma.sync.aligned.m16n8k16.row.col.f32.bf16.bf16.f32 "
        "{%0,%1,%2,%3}, {%4,%5,%6,%7}, {%8,%9}, {%0,%1,%2,%3};"
        : "+f"(c[0]), "+f"(c[1]), "+f"(c[2]), "+f"(c[3])
        : "r"(a[0]), "r"(a[1]), "r"(a[2]), "r"(a[3]), "r"(b0), "r"(b1));
}
static __device__ __forceinline__ void cp16(uint32_t dst, const void* src) {
    asm volatile("cp.async.cg.shared.global [%0], [%1], 16;" :: "r"(dst), "l"(src));
}
static __device__ __forceinline__ void cp_commit() {
    asm volatile("cp.async.commit_group;" ::: "memory");
}
static __device__ __forceinline__ void cp_wait0() {
    asm volatile("cp.async.wait_group 0;" ::: "memory");
}
static __device__ __forceinline__ uint32_t packbf(float a, float b) {
    __nv_bfloat162 v;
    v.x = __float2bfloat16(a);
    v.y = __float2bfloat16(b);
    return *(uint32_t*)&v;
}

// ---------------- prep: fold BN, bf16, ldsm-swizzle weights ------------
__global__ void prep_kernel(const float* __restrict__ w1, const float* __restrict__ g1,
                            const float* __restrict__ b1, const float* __restrict__ m1,
                            const float* __restrict__ v1,
                            const float* __restrict__ w2, const float* __restrict__ g2,
                            const float* __restrict__ b2, const float* __restrict__ m2,
                            const float* __restrict__ v2) {
    int idx = blockIdx.x*256 + threadIdx.x;
    if (idx < 2*9*4096) {
        int cv = idx / 36864;
        int r  = idx - cv*36864;
        int s  = r >> 12;
        int q  = r & 4095;
        int oc = q >> 6;
        int ic = q & 63;
        const float* w = cv ? w2 : w1;
        const float* g = cv ? g2 : g1;
        const float* v = cv ? v2 : v1;
        float f = w[(oc*C + ic)*9 + s] * (g[oc] * rsqrtf(v[oc] + EPS));
        uint32_t e = (uint32_t)oc*64 + ((uint32_t)ic ^ (((uint32_t)oc & 7u) << 3));
        __nv_bfloat16* dst = (__nv_bfloat16*)(cv ? g_wbm2 : g_wbm1) + (size_t)s*4096;
        dst[e] = __float2bfloat16(f);
    }
    if (idx < C) {
        g_bias1[idx] = b1[idx] - m1[idx]*g1[idx]*rsqrtf(v1[idx] + EPS);
        g_bias2[idx] = b2[idx] - m2[idx]*g2[idx]*rsqrtf(v2[idx] + EPS);
    }
}

// ---------------- HMMA conv: bf16 implicit GEMM ------------------------
// STORE=1: reads x (fp32 NCHW, fused transpose+cvt), writes g_f1
// STORE=0: reads g_f1 (bf16 pixel-major, cp.async fill), writes pooled partials
template<int STORE>
__launch_bounds__(256, 5)
__global__ void conv_mma(const float* __restrict__ xin) {
    extern __shared__ uint8_t sm[];
    const uint32_t sb = smem_u32(sm);

    const int tid  = threadIdx.x;
    const int lane = tid & 31;
    const int wrp  = tid >> 5;
    const int x0 = blockIdx.x * 32, y0 = blockIdx.y * 4;
    const int b  = blockIdx.z;

    const uint32_t* gwb = STORE ? g_wbm1 : g_wbm2;
    const float*   bias = STORE ? g_bias1 : g_bias2;

    // prefetch B slice 0 (8KB)
    {
        uint32_t dst = sb + OFF_B0;
        #pragma unroll
        for (int i = 0; i < 2; i++)
            cp16(dst + (tid + i*256)*16, gwb + (size_t)(tid + i*256)*4);
        cp_commit();
    }

    // fill halo tile (bf16, swizzled rows of 128B)
    if (STORE) {
        // fused transpose: read NCHW fp32, convert, store [px][ch] swizzled
        const float* inb = xin + (size_t)b * CHW;
        for (int i = tid; i < TPX*8; i += 256) {
            int ch8 = i / TPX, pxl = i - ch8*TPX;
            int rr = pxl / 34, cc = pxl - rr*34;
            int py = y0 + rr - 1, px = x0 + cc - 1;
            uint4 v = make_uint4(0,0,0,0);
            if (py >= 0 && py < H && px >= 0 && px < W) {
                const float* p = inb + (size_t)(ch8*8)*HW + py*W + px;
                v.x = packbf(p[0],    p[HW]);
                v.y = packbf(p[2*HW], p[3*HW]);
                v.z = packbf(p[4*HW], p[5*HW]);
                v.w = packbf(p[6*HW], p[7*HW]);
            }
            uint32_t boff = (uint32_t)pxl*128 + (((uint32_t)ch8*16) ^ (((uint32_t)pxl & 7u) << 4));
            *(uint4*)(sm + OFF_TH + boff) = v;
        }
    } else {
        // cp.async fill: 16B per (pixel, 8-ch group), zero halo via STS
        const uint32_t* f1b = g_f1 + ((size_t)b*HW << 5);
        for (int i = tid; i < TPX*8; i += 256) {
            int pxl = i >> 3, ch8 = i & 7;
            int rr = pxl / 34, cc = pxl - rr*34;
            int py = y0 + rr - 1, px = x0 + cc - 1;
            uint32_t boff = (uint32_t)pxl*128 + (((uint32_t)ch8*16) ^ (((uint32_t)pxl & 7u) << 4));
            if (py >= 0 && py < H && px >= 0 && px < W) {
                cp16(sb + OFF_TH + boff, f1b + ((size_t)(py*W + px) << 5) + ch8*4);
            } else {
                *(uint4*)(sm + OFF_TH + boff) = make_uint4(0,0,0,0);
            }
        }
        cp_commit();
    }

    // per-lane ldsm address components
    const int g  = lane >> 3, lr = lane & 7;
    const int mb = (wrp & 3) * 32;
    const int nb = (wrp >> 2) * 32;
    const uint32_t kaddA = (g >= 2) ? 16u : 0u;
    const uint32_t kaddB = (uint32_t)(g & 1) << 4;
    int pA[2];
    uint32_t bAddr[2];
    #pragma unroll
    for (int f = 0; f < 2; f++) {
        int p = mb + f*16 + ((g & 1) << 3) + lr;
        pA[f] = (p >> 5)*34 + (p & 31);
        int oc = nb + f*16 + ((g >= 2) ? 8 : 0) + lr;
        bAddr[f] = (uint32_t)oc*128 + (kaddB ^ ((((uint32_t)oc & 7u) << 4)));
    }

    float acc[2][4][4];
    #pragma unroll
    for (int m = 0; m < 2; m++)
        #pragma unroll
        for (int n = 0; n < 4; n++)
            #pragma unroll
            for (int q = 0; q < 4; q++) acc[m][n][q] = 0.f;

    for (int s = 0; s < 9; s++) {
        cp_wait0();
        __syncthreads();
        if (s < 8) {
            uint32_t dst = sb + (((s+1) & 1) ? OFF_B1 : OFF_B0);
            const uint32_t* src = gwb + (size_t)(s+1)*2048;
            #pragma unroll
            for (int i = 0; i < 2; i++)
                cp16(dst + (tid + i*256)*16, src + (size_t)(tid + i*256)*4);
            cp_commit();
        }
        const int ky = s / 3, kx = s - 3*(s/3);
        const int soff = ky*34 + kx;
        const uint32_t bbuf = sb + ((s & 1) ? OFF_B1 : OFF_B0);

        #pragma unroll
        for (int kc = 0; kc < 4; kc++) {
            uint32_t AH[2][4];
            #pragma unroll
            for (int f = 0; f < 2; f++) {
                uint32_t pxl = (uint32_t)(pA[f] + soff);
                uint32_t aoff = pxl*128 + (((uint32_t)kc*32 + kaddA) ^ ((pxl & 7u) << 4));
                ldsm4(AH[f], sb + OFF_TH + aoff);
            }
            #pragma unroll
            for (int f = 0; f < 2; f++) {
                uint32_t r[4];
                ldsm4(r, bbuf + (bAddr[f] ^ ((uint32_t)kc*32)));
                mma16816(acc[0][2*f],   AH[0], r[0], r[1]);
                mma16816(acc[0][2*f+1], AH[0], r[2], r[3]);
                mma16816(acc[1][2*f],   AH[1], r[0], r[1]);
                mma16816(acc[1][2*f+1], AH[1], r[2], r[3]);
            }
        }
    }

    // ---------------- epilogue ----------------
    if (STORE) {
        uint32_t* f1b = g_f1 + ((size_t)b*HW << 5);
        #pragma unroll
        for (int m = 0; m < 2; m++) {
            #pragma unroll
            for (int n = 0; n < 4; n++) {
                int oc = nb + n*8 + (lane & 3)*2;
                float b0 = bias[oc], b1v = bias[oc+1];
                #pragma unroll
                for (int hh = 0; hh < 2; hh++) {
                    int p = mb + m*16 + (lane >> 2) + hh*8;
                    int py = y0 + (p >> 5), px = x0 + (p & 31);
                    f1b[((size_t)(py*W + px) << 5) + (oc >> 1)] =
                        packbf(fmaxf(acc[m][n][hh*2]   + b0,  0.f),
                               fmaxf(acc[m][n][hh*2+1] + b1v, 0.f));
                }
            }
        }
    } else {
        float cs[4][2];
        #pragma unroll
        for (int n = 0; n < 4; n++) {
            int oc = nb + n*8 + (lane & 3)*2;
            float b0 = bias[oc], b1v = bias[oc+1];
            float s0 = 0.f, s1 = 0.f;
            #pragma unroll
            for (int m = 0; m < 2; m++) {
                s0 += fmaxf(acc[m][n][0] + b0, 0.f) + fmaxf(acc[m][n][2] + b0, 0.f);
                s1 += fmaxf(acc[m][n][1] + b1v, 0.f) + fmaxf(acc[m][n][3] + b1v, 0.f);
            }
            #pragma unroll
            for (int d = 4; d < 32; d <<= 1) {
                s0 += __shfl_xor_sync(0xffffffffu, s0, d);
                s1 += __shfl_xor_sync(0xffffffffu, s1, d);
            }
            cs[n][0] = s0; cs[n][1] = s1;
        }
        __syncthreads();                       // tile reads done -> reuse as pool
        float* pool = (float*)(sm + OFF_TH);   // [4 mrow][64 oc]
        if (lane < 4) {
            #pragma unroll
            for (int n = 0; n < 4; n++) {
                int oc = nb + n*8 + lane*2;
                pool[(wrp & 3)*64 + oc]     = cs[n][0];
                pool[(wrp & 3)*64 + oc + 1] = cs[n][1];
            }
        }
        __syncthreads();
        if (tid < C) {
            float s = pool[tid] + pool[64 + tid] + pool[128 + tid] + pool[192 + tid];
            int tileIdx = blockIdx.y * NTX + blockIdx.x;
            g_part[((size_t)b*NT + tileIdx)*C + tid] = s;
        }
    }
}

// ---------------- tailA: per-sample pool finish + MLP -> logits --------
__launch_bounds__(512)
__global__ void tailA_kernel(const float* __restrict__ w1, const float* __restrict__ b1,
                             const float* __restrict__ w2, const float* __restrict__ b2) {
    __shared__ float red[512];
    __shared__ float feat[64];
    __shared__ float hidden[128];
    const int tid = threadIdx.x;
    const int b = blockIdx.x;

    {
        int c = tid & 63, grp = tid >> 6;
        float s = 0.f;
        const float* gp = g_part + ((size_t)b*NT + grp*9)*C + c;
        #pragma unroll
        for (int t = 0; t < 9; t++) s += gp[t*C];
        red[tid] = s;
    }
    __syncthreads();
    if (tid < 64) {
        float s = 0.f;
        #pragma unroll
        for (int g2 = 0; g2 < 8; g2++) s += red[g2*64 + tid];
        feat[tid] = s * (1.f/(float)HW);
    }
    __syncthreads();

    {
        int j = tid >> 2, part = tid & 3;
        float h = 0.f;
        #pragma unroll
        for (int ii = 0; ii < 16; ii++) {
            int i = part*16 + ii;
            h += feat[i] * w1[i*HID + j];
        }
        h += __shfl_xor_sync(0xffffffffu, h, 1);
        h += __shfl_xor_sync(0xffffffffu, h, 2);
        if (part == 0) hidden[j] = fmaxf(h + b1[j], 0.f);
    }
    __syncthreads();

    {
        int t = tid >> 3, part = tid & 7;
        float s = 0.f;
        #pragma unroll
        for (int jj = 0; jj < 16; jj++) {
            int j = part*16 + jj;
            s += hidden[j] * w2[j*TT + t];
        }
        s += __shfl_xor_sync(0xffffffffu, s, 1);
        s += __shfl_xor_sync(0xffffffffu, s, 2);
        s += __shfl_xor_sync(0xffffffffu, s, 4);
        if (part == 0) g_logits[b*TT + t] = s + b2[t];
    }
}

// ---------------- tailB: softmax, loss, EMA, outputs -------------------
__launch_bounds__(1024)
__global__ void tailB_kernel(const float* __restrict__ ref_x, const int* __restrict__ ref_types,
                             const float* __restrict__ ref_proj, float* __restrict__ dout) {
    extern __shared__ float smf[];
    float* logit  = smf;             // [32][64] -> becomes type_weights
    float* refnew = logit + 2048;    // [64][64]
    float* refx   = refnew + 4096;   // [32][64]
    float* lossv  = refx + 2048;     // [32]
    float* coeff  = lossv + 32;      // [32]
    float* decay  = coeff + 32;      // [64]
    int*   st     = (int*)(decay + 64);

    const int tid = threadIdx.x;
    const int NTH = 1024;
    if (tid < BS) st[tid] = ref_types[tid];
    for (int i = tid; i < BS*TT; i += NTH) logit[i] = g_logits[i];
    for (int i = tid; i < BS*C; i += NTH) refx[i] = ref_x[i];
    __syncthreads();

    {
        const int wp = tid >> 5, ln = tid & 31;
        float* lr = logit + wp*TT;
        float a = lr[ln], c2 = lr[ln + 32];
        float tgt = lr[st[wp]];
        float mx = fmaxf(a, c2);
        #pragma unroll
        for (int s = 16; s; s >>= 1) mx = fmaxf(mx, __shfl_xor_sync(0xffffffffu, mx, s));
        float ea = expf(a - mx), eb = expf(c2 - mx);
        float sum = ea + eb;
        #pragma unroll
        for (int s = 16; s; s >>= 1) sum += __shfl_xor_sync(0xffffffffu, sum, s);
        if (ln == 0) lossv[wp] = mx + logf(sum) - tgt;
        float inv = 1.f / sum;
        __syncwarp();
        lr[ln]      = ea * inv;
        lr[ln + 32] = eb * inv;
    }
    if (tid < TT) {
        int cnt = 0;
        for (int i = 0; i < BS; i++) cnt += (st[i] == tid);
        float r = 1.f;
        for (int q = 0; q < cnt; q++) r *= 0.99f;
        decay[tid] = r;
    }
    if (tid >= 64 && tid < 96) {
        int i = tid - 64;
        int after = 0;
        for (int j = i + 1; j < BS; j++) after += (st[j] == st[i]);
        float r = 0.01f;
        for (int q = 0; q < after; q++) r *= 0.99f;
        coeff[i] = r;
    }
    __syncthreads();

    for (int idx = tid; idx < TT*C; idx += NTH) {
        int t = idx >> 6, c = idx & 63;
        float v = decay[t] * ref_proj[idx];
        #pragma unroll 8
        for (int i = 0; i < BS; i++)
            if (st[i] == t) v += coeff[i] * refx[i*C + c];
        refnew[idx] = v;
        dout[2049 + idx] = v;
    }
    __syncthreads();

    for (int idx = tid; idx < BS*C; idx += NTH) {
        int bb = idx >> 6, c = idx & 63;
        float s = refx[idx];
        const float* twr = logit + bb*TT;
        #pragma unroll 16
        for (int t = 0; t < TT; t++) s += twr[t] * refnew[t*C + c];
        dout[idx] = s;
    }
    if (tid == 0) {
        float s = 0.f;
        for (int i = 0; i < BS; i++) s += lossv[i];
        dout[2048] = s * (1.f/(float)BS);
    }
}

// ---------------- launch ----------------
extern "C" void kernel_launch(void* const* d_in, const int* in_sizes, int n_in,
                              void* d_out, int out_size) {
    const float* x        = (const float*)d_in[0];
    const float* ref_x    = (const float*)d_in[1];
    const int*   ref_types= (const int*)  d_in[2];
    const float* conv1_w  = (const float*)d_in[3];
    const float* bn1_g    = (const float*)d_in[4];
    const float* bn1_b    = (const float*)d_in[5];
    const float* bn1_m    = (const float*)d_in[6];
    const float* bn1_v    = (const float*)d_in[7];
    const float* conv2_w  = (const float*)d_in[8];
    const float* bn2_g    = (const float*)d_in[9];
    const float* bn2_b    = (const float*)d_in[10];
    const float* bn2_m    = (const float*)d_in[11];
    const float* bn2_v    = (const float*)d_in[12];
    const float* mlp_w1   = (const float*)d_in[13];
    const float* mlp_b1   = (const float*)d_in[14];
    const float* mlp_w2   = (const float*)d_in[15];
    const float* mlp_b2   = (const float*)d_in[16];
    const float* ref_proj = (const float*)d_in[17];
    float* out = (float*)d_out;

    cudaFuncSetAttribute(conv_mma<1>, cudaFuncAttributeMaxDynamicSharedMemorySize, CONV_SMEM);
    cudaFuncSetAttribute(conv_mma<0>, cudaFuncAttributeMaxDynamicSharedMemorySize, CONV_SMEM);
    cudaFuncSetAttribute(tailB_kernel, cudaFuncAttributeMaxDynamicSharedMemorySize, TAILB_SMEM_BYTES);

    prep_kernel<<<288, 256>>>(conv1_w, bn1_g, bn1_b, bn1_m, bn1_v,
                              conv2_w, bn2_g, bn2_b, bn2_m, bn2_v);

    dim3 cgrid(NTX, NTY, BS);
    conv_mma<1><<<cgrid, 256, CONV_SMEM>>>(x);
    conv_mma<0><<<cgrid, 256, CONV_SMEM>>>(x);

    tailA_kernel<<<BS, 512>>>(mlp_w1, mlp_b1, mlp_w2, mlp_b2);
    tailB_kernel<<<1, 1024, TAILB_SMEM_BYTES>>>(ref_x, ref_types, ref_proj, out);
}

// round 14
// speedup vs baseline: 4.0117x; 2.1623x over previous
#include <cuda_runtime.h>
#include <cuda_bf16.h>
#include <cstdint>

// ---------------- problem constants ----------------
#define BS   32
#define C    64
#define H    96
#define W    96
#define HW   (H*W)
#define CHW  ((size_t)C*HW)
#define TT   64
#define HID  128
#define EPS  1e-5f

// conv tiling: CTA = 4 rows x 32 cols = 128 px (M), 64 oc (N), K = 9*64
#define NTX 3
#define NTY 24
#define NT  (NTX*NTY)        // 72 tiles/image

// halo tile: 6 rows x 34 cols = 204 pixel-rows, each 64 bf16 = 128B
#define TPX 204
#define OFF_TH 0
#define OFF_B0 26624
#define OFF_B1 34816
#define CONV_SMEM 43008      // 4 CTAs/SM (172KB < 228KB), 64 regs/thread

#define TAILB_SMEM_FLOATS (2048+4096+2048+160)
#define TAILB_SMEM_BYTES  (TAILB_SMEM_FLOATS*4)

// ---------------- device scratch ----------------
__device__ uint32_t g_f1[BS*HW*32];   // conv1 out, pixel-major bf16 (2 ch per u32)
__device__ uint32_t g_wbm1[9*2048];   // weights: per slice 8KB bf16, ldsm-swizzled
__device__ uint32_t g_wbm2[9*2048];
__device__ float    g_bias1[C];
__device__ float    g_bias2[C];
__device__ float    g_part[BS*NT*C];
__device__ float    g_logits[BS*TT];

// ---------------- helpers ----------------
static __device__ __forceinline__ uint32_t smem_u32(const void* p) {
    uint32_t a;
    asm("{ .reg .u64 t; cvta.to.shared.u64 t, %1; cvt.u32.u64 %0, t; }" : "=r"(a) : "l"(p));
    return a;
}
static __device__ __forceinline__ void ldsm4(uint32_t* r, uint32_t a) {
    asm volatile("ldmatrix.sync.aligned.m8n8.x4.shared.b16 {%0,%1,%2,%3}, [%4];"
        : "=r"(r[0]), "=r"(r[1]), "=r"(r[2]), "=r"(r[3]) : "r"(a));
}
static __device__ __forceinline__ void mma16816(float* c, const uint32_t* a, uint32_t b0, uint32_t b1) {
    asm volatile("mma.sync.aligned.m16n8k16.row.col.f32.bf16.bf16.f32 "
        "{%0,%1,%2,%3}, {%4,%5,%6,%7}, {%8,%9}, {%0,%1,%2,%3};"
        : "+f"(c[0]), "+f"(c[1]), "+f"(c[2]), "+f"(c[3])
        : "r"(a[0]), "r"(a[1]), "r"(a[2]), "r"(a[3]), "r"(b0), "r"(b1));
}
static __device__ __forceinline__ void cp16(uint32_t dst, const void* src) {
    asm volatile("cp.async.cg.shared.global [%0], [%1], 16;" :: "r"(dst), "l"(src));
}
static __device__ __forceinline__ void cp_commit() {
    asm volatile("cp.async.commit_group;" ::: "memory");
}
static __device__ __forceinline__ void cp_wait0() {
    asm volatile("cp.async.wait_group 0;" ::: "memory");
}
static __device__ __forceinline__ uint32_t packbf(float a, float b) {
    __nv_bfloat162 v;
    v.x = __float2bfloat16(a);
    v.y = __float2bfloat16(b);
    return *(uint32_t*)&v;
}

// ---------------- prep: fold BN, bf16, ldsm-swizzle weights ------------
__global__ void prep_kernel(const float* __restrict__ w1, const float* __restrict__ g1,
                            const float* __restrict__ b1, const float* __restrict__ m1,
                            const float* __restrict__ v1,
                            const float* __restrict__ w2, const float* __restrict__ g2,
                            const float* __restrict__ b2, const float* __restrict__ m2,
                            const float* __restrict__ v2) {
    int idx = blockIdx.x*256 + threadIdx.x;
    if (idx < 2*9*4096) {
        int cv = idx / 36864;
        int r  = idx - cv*36864;
        int s  = r >> 12;
        int q  = r & 4095;
        int oc = q >> 6;
        int ic = q & 63;
        const float* w = cv ? w2 : w1;
        const float* g = cv ? g2 : g1;
        const float* v = cv ? v2 : v1;
        float f = w[(oc*C + ic)*9 + s] * (g[oc] * rsqrtf(v[oc] + EPS));
        uint32_t e = (uint32_t)oc*64 + ((uint32_t)ic ^ (((uint32_t)oc & 7u) << 3));
        __nv_bfloat16* dst = (__nv_bfloat16*)(cv ? g_wbm2 : g_wbm1) + (size_t)s*4096;
        dst[e] = __float2bfloat16(f);
    }
    if (idx < C) {
        g_bias1[idx] = b1[idx] - m1[idx]*g1[idx]*rsqrtf(v1[idx] + EPS);
        g_bias2[idx] = b2[idx] - m2[idx]*g2[idx]*rsqrtf(v2[idx] + EPS);
    }
}

// ---------------- HMMA conv: bf16 implicit GEMM ------------------------
// STORE=1: reads x (fp32 NCHW, fused transpose+cvt), writes g_f1
// STORE=0: reads g_f1 (bf16 pixel-major, cp.async fill), writes pooled partials
template<int STORE>
__launch_bounds__(256, 4)
__global__ void conv_mma(const float* __restrict__ xin) {
    extern __shared__ uint8_t sm[];
    const uint32_t sb = smem_u32(sm);

    const int tid  = threadIdx.x;
    const int lane = tid & 31;
    const int wrp  = tid >> 5;
    const int x0 = blockIdx.x * 32, y0 = blockIdx.y * 4;
    const int b  = blockIdx.z;

    const uint32_t* gwb = STORE ? g_wbm1 : g_wbm2;
    const float*   bias = STORE ? g_bias1 : g_bias2;

    // prefetch B slice 0 (8KB)
    {
        uint32_t dst = sb + OFF_B0;
        #pragma unroll
        for (int i = 0; i < 2; i++)
            cp16(dst + (tid + i*256)*16, gwb + (size_t)(tid + i*256)*4);
        cp_commit();
    }

    // fill halo tile (bf16, swizzled rows of 128B)
    if (STORE) {
        // fused transpose: read NCHW fp32, convert, store [px][ch] swizzled
        const float* inb = xin + (size_t)b * CHW;
        for (int i = tid; i < TPX*8; i += 256) {
            int ch8 = i / TPX, pxl = i - ch8*TPX;
            int rr = pxl / 34, cc = pxl - rr*34;
            int py = y0 + rr - 1, px = x0 + cc - 1;
            uint4 v = make_uint4(0,0,0,0);
            if (py >= 0 && py < H && px >= 0 && px < W) {
                const float* p = inb + (size_t)(ch8*8)*HW + py*W + px;
                v.x = packbf(p[0],    p[HW]);
                v.y = packbf(p[2*HW], p[3*HW]);
                v.z = packbf(p[4*HW], p[5*HW]);
                v.w = packbf(p[6*HW], p[7*HW]);
            }
            uint32_t boff = (uint32_t)pxl*128 + (((uint32_t)ch8*16) ^ (((uint32_t)pxl & 7u) << 4));
            *(uint4*)(sm + OFF_TH + boff) = v;
        }
    } else {
        // cp.async fill: 16B per (pixel, 8-ch group), zero halo via STS
        const uint32_t* f1b = g_f1 + ((size_t)b*HW << 5);
        for (int i = tid; i < TPX*8; i += 256) {
            int pxl = i >> 3, ch8 = i & 7;
            int rr = pxl / 34, cc = pxl - rr*34;
            int py = y0 + rr - 1, px = x0 + cc - 1;
            uint32_t boff = (uint32_t)pxl*128 + (((uint32_t)ch8*16) ^ (((uint32_t)pxl & 7u) << 4));
            if (py >= 0 && py < H && px >= 0 && px < W) {
                cp16(sb + OFF_TH + boff, f1b + ((size_t)(py*W + px) << 5) + ch8*4);
            } else {
                *(uint4*)(sm + OFF_TH + boff) = make_uint4(0,0,0,0);
            }
        }
        cp_commit();
    }

    // per-lane ldsm address components
    const int g  = lane >> 3, lr = lane & 7;
    const int mb = (wrp & 3) * 32;
    const int nb = (wrp >> 2) * 32;
    const uint32_t kaddA = (g >= 2) ? 16u : 0u;
    const uint32_t kaddB = (uint32_t)(g & 1) << 4;
    int pA[2];
    uint32_t bAddr[2];
    #pragma unroll
    for (int f = 0; f < 2; f++) {
        int p = mb + f*16 + ((g & 1) << 3) + lr;
        pA[f] = (p >> 5)*34 + (p & 31);
        int oc = nb + f*16 + ((g >= 2) ? 8 : 0) + lr;
        bAddr[f] = (uint32_t)oc*128 + (kaddB ^ ((((uint32_t)oc & 7u) << 4)));
    }

    float acc[2][4][4];
    #pragma unroll
    for (int m = 0; m < 2; m++)
        #pragma unroll
        for (int n = 0; n < 4; n++)
            #pragma unroll
            for (int q = 0; q < 4; q++) acc[m][n][q] = 0.f;

    for (int s = 0; s < 9; s++) {
        cp_wait0();
        __syncthreads();
        if (s < 8) {
            uint32_t dst = sb + (((s+1) & 1) ? OFF_B1 : OFF_B0);
            const uint32_t* src = gwb + (size_t)(s+1)*2048;
            #pragma unroll
            for (int i = 0; i < 2; i++)
                cp16(dst + (tid + i*256)*16, src + (size_t)(tid + i*256)*4);
            cp_commit();
        }
        const int ky = s / 3, kx = s - 3*(s/3);
        const int soff = ky*34 + kx;
        const uint32_t bbuf = sb + ((s & 1) ? OFF_B1 : OFF_B0);

        #pragma unroll
        for (int kc = 0; kc < 4; kc++) {
            uint32_t AH[2][4];
            #pragma unroll
            for (int f = 0; f < 2; f++) {
                uint32_t pxl = (uint32_t)(pA[f] + soff);
                uint32_t aoff = pxl*128 + (((uint32_t)kc*32 + kaddA) ^ ((pxl & 7u) << 4));
                ldsm4(AH[f], sb + OFF_TH + aoff);
            }
            #pragma unroll
            for (int f = 0; f < 2; f++) {
                uint32_t r[4];
                ldsm4(r, bbuf + (bAddr[f] ^ ((uint32_t)kc*32)));
                mma16816(acc[0][2*f],   AH[0], r[0], r[1]);
                mma16816(acc[0][2*f+1], AH[0], r[2], r[3]);
                mma16816(acc[1][2*f],   AH[1], r[0], r[1]);
                mma16816(acc[1][2*f+1], AH[1], r[2], r[3]);
            }
        }
    }

    // ---------------- epilogue ----------------
    if (STORE) {
        uint32_t* f1b = g_f1 + ((size_t)b*HW << 5);
        #pragma unroll
        for (int m = 0; m < 2; m++) {
            #pragma unroll
            for (int n = 0; n < 4; n++) {
                int oc = nb + n*8 + (lane & 3)*2;
                float b0 = bias[oc], b1v = bias[oc+1];
                #pragma unroll
                for (int hh = 0; hh < 2; hh++) {
                    int p = mb + m*16 + (lane >> 2) + hh*8;
                    int py = y0 + (p >> 5), px = x0 + (p & 31);
                    f1b[((size_t)(py*W + px) << 5) + (oc >> 1)] =
                        packbf(fmaxf(acc[m][n][hh*2]   + b0,  0.f),
                               fmaxf(acc[m][n][hh*2+1] + b1v, 0.f));
                }
            }
        }
    } else {
        float cs[4][2];
        #pragma unroll
        for (int n = 0; n < 4; n++) {
            int oc = nb + n*8 + (lane & 3)*2;
            float b0 = bias[oc], b1v = bias[oc+1];
            float s0 = 0.f, s1 = 0.f;
            #pragma unroll
            for (int m = 0; m < 2; m++) {
                s0 += fmaxf(acc[m][n][0] + b0, 0.f) + fmaxf(acc[m][n][2] + b0, 0.f);
                s1 += fmaxf(acc[m][n][1] + b1v, 0.f) + fmaxf(acc[m][n][3] + b1v, 0.f);
            }
            #pragma unroll
            for (int d = 4; d < 32; d <<= 1) {
                s0 += __shfl_xor_sync(0xffffffffu, s0, d);
                s1 += __shfl_xor_sync(0xffffffffu, s1, d);
            }
            cs[n][0] = s0; cs[n][1] = s1;
        }
        __syncthreads();                       // tile reads done -> reuse as pool
        float* pool = (float*)(sm + OFF_TH);   // [4 mrow][64 oc]
        if (lane < 4) {
            #pragma unroll
            for (int n = 0; n < 4; n++) {
                int oc = nb + n*8 + lane*2;
                pool[(wrp & 3)*64 + oc]     = cs[n][0];
                pool[(wrp & 3)*64 + oc + 1] = cs[n][1];
            }
        }
        __syncthreads();
        if (tid < C) {
            float s = pool[tid] + pool[64 + tid] + pool[128 + tid] + pool[192 + tid];
            int tileIdx = blockIdx.y * NTX + blockIdx.x;
            g_part[((size_t)b*NT + tileIdx)*C + tid] = s;
        }
    }
}

// ---------------- tailA: per-sample pool finish + MLP -> logits --------
__launch_bounds__(512)
__global__ void tailA_kernel(const float* __restrict__ w1, const float* __restrict__ b1,
                             const float* __restrict__ w2, const float* __restrict__ b2) {
    __shared__ float red[512];
    __shared__ float feat[64];
    __shared__ float hidden[128];
    const int tid = threadIdx.x;
    const int b = blockIdx.x;

    {
        int c = tid & 63, grp = tid >> 6;
        float s = 0.f;
        const float* gp = g_part + ((size_t)b*NT + grp*9)*C + c;
        #pragma unroll
        for (int t = 0; t < 9; t++) s += gp[t*C];
        red[tid] = s;
    }
    __syncthreads();
    if (tid < 64) {
        float s = 0.f;
        #pragma unroll
        for (int g2 = 0; g2 < 8; g2++) s += red[g2*64 + tid];
        feat[tid] = s * (1.f/(float)HW);
    }
    __syncthreads();

    {
        int j = tid >> 2, part = tid & 3;
        float h = 0.f;
        #pragma unroll
        for (int ii = 0; ii < 16; ii++) {
            int i = part*16 + ii;
            h += feat[i] * w1[i*HID + j];
        }
        h += __shfl_xor_sync(0xffffffffu, h, 1);
        h += __shfl_xor_sync(0xffffffffu, h, 2);
        if (part == 0) hidden[j] = fmaxf(h + b1[j], 0.f);
    }
    __syncthreads();

    {
        int t = tid >> 3, part = tid & 7;
        float s = 0.f;
        #pragma unroll
        for (int jj = 0; jj < 16; jj++) {
            int j = part*16 + jj;
            s += hidden[j] * w2[j*TT + t];
        }
        s += __shfl_xor_sync(0xffffffffu, s, 1);
        s += __shfl_xor_sync(0xffffffffu, s, 2);
        s += __shfl_xor_sync(0xffffffffu, s, 4);
        if (part == 0) g_logits[b*TT + t] = s + b2[t];
    }
}

// ---------------- tailB: softmax, loss, EMA, outputs -------------------
__launch_bounds__(1024)
__global__ void tailB_kernel(const float* __restrict__ ref_x, const int* __restrict__ ref_types,
                             const float* __restrict__ ref_proj, float* __restrict__ dout) {
    extern __shared__ float smf[];
    float* logit  = smf;             // [32][64] -> becomes type_weights
    float* refnew = logit + 2048;    // [64][64]
    float* refx   = refnew + 4096;   // [32][64]
    float* lossv  = refx + 2048;     // [32]
    float* coeff  = lossv + 32;      // [32]
    float* decay  = coeff + 32;      // [64]
    int*   st     = (int*)(decay + 64);

    const int tid = threadIdx.x;
    const int NTH = 1024;
    if (tid < BS) st[tid] = ref_types[tid];
    for (int i = tid; i < BS*TT; i += NTH) logit[i] = g_logits[i];
    for (int i = tid; i < BS*C; i += NTH) refx[i] = ref_x[i];
    __syncthreads();

    {
        const int wp = tid >> 5, ln = tid & 31;
        float* lr = logit + wp*TT;
        float a = lr[ln], c2 = lr[ln + 32];
        float tgt = lr[st[wp]];
        float mx = fmaxf(a, c2);
        #pragma unroll
        for (int s = 16; s; s >>= 1) mx = fmaxf(mx, __shfl_xor_sync(0xffffffffu, mx, s));
        float ea = expf(a - mx), eb = expf(c2 - mx);
        float sum = ea + eb;
        #pragma unroll
        for (int s = 16; s; s >>= 1) sum += __shfl_xor_sync(0xffffffffu, sum, s);
        if (ln == 0) lossv[wp] = mx + logf(sum) - tgt;
        float inv = 1.f / sum;
        __syncwarp();
        lr[ln]      = ea * inv;
        lr[ln + 32] = eb * inv;
    }
    if (tid < TT) {
        int cnt = 0;
        for (int i = 0; i < BS; i++) cnt += (st[i] == tid);
        float r = 1.f;
        for (int q = 0; q < cnt; q++) r *= 0.99f;
        decay[tid] = r;
    }
    if (tid >= 64 && tid < 96) {
        int i = tid - 64;
        int after = 0;
        for (int j = i + 1; j < BS; j++) after += (st[j] == st[i]);
        float r = 0.01f;
        for (int q = 0; q < after; q++) r *= 0.99f;
        coeff[i] = r;
    }
    __syncthreads();

    for (int idx = tid; idx < TT*C; idx += NTH) {
        int t = idx >> 6, c = idx & 63;
        float v = decay[t] * ref_proj[idx];
        #pragma unroll 8
        for (int i = 0; i < BS; i++)
            if (st[i] == t) v += coeff[i] * refx[i*C + c];
        refnew[idx] = v;
        dout[2049 + idx] = v;
    }
    __syncthreads();

    for (int idx = tid; idx < BS*C; idx += NTH) {
        int bb = idx >> 6, c = idx & 63;
        float s = refx[idx];
        const float* twr = logit + bb*TT;
        #pragma unroll 16
        for (int t = 0; t < TT; t++) s += twr[t] * refnew[t*C + c];
        dout[idx] = s;
    }
    if (tid == 0) {
        float s = 0.f;
        for (int i = 0; i < BS; i++) s += lossv[i];
        dout[2048] = s * (1.f/(float)BS);
    }
}

// ---------------- launch ----------------
extern "C" void kernel_launch(void* const* d_in, const int* in_sizes, int n_in,
                              void* d_out, int out_size) {
    const float* x        = (const float*)d_in[0];
    const float* ref_x    = (const float*)d_in[1];
    const int*   ref_types= (const int*)  d_in[2];
    const float* conv1_w  = (const float*)d_in[3];
    const float* bn1_g    = (const float*)d_in[4];
    const float* bn1_b    = (const float*)d_in[5];
    const float* bn1_m    = (const float*)d_in[6];
    const float* bn1_v    = (const float*)d_in[7];
    const float* conv2_w  = (const float*)d_in[8];
    const float* bn2_g    = (const float*)d_in[9];
    const float* bn2_b    = (const float*)d_in[10];
    const float* bn2_m    = (const float*)d_in[11];
    const float* bn2_v    = (const float*)d_in[12];
    const float* mlp_w1   = (const float*)d_in[13];
    const float* mlp_b1   = (const float*)d_in[14];
    const float* mlp_w2   = (const float*)d_in[15];
    const float* mlp_b2   = (const float*)d_in[16];
    const float* ref_proj = (const float*)d_in[17];
    float* out = (float*)d_out;

    cudaFuncSetAttribute(conv_mma<1>, cudaFuncAttributeMaxDynamicSharedMemorySize, CONV_SMEM);
    cudaFuncSetAttribute(conv_mma<0>, cudaFuncAttributeMaxDynamicSharedMemorySize, CONV_SMEM);
    cudaFuncSetAttribute(tailB_kernel, cudaFuncAttributeMaxDynamicSharedMemorySize, TAILB_SMEM_BYTES);

    prep_kernel<<<288, 256>>>(conv1_w, bn1_g, bn1_b, bn1_m, bn1_v,
                              conv2_w, bn2_g, bn2_b, bn2_m, bn2_v);

    dim3 cgrid(NTX, NTY, BS);
    conv_mma<1><<<cgrid, 256, CONV_SMEM>>>(x);
    conv_mma<0><<<cgrid, 256, CONV_SMEM>>>(x);

    tailA_kernel<<<BS, 512>>>(mlp_w1, mlp_b1, mlp_w2, mlp_b2);
    tailB_kernel<<<1, 1024, TAILB_SMEM_BYTES>>>(ref_x, ref_types, ref_proj, out);
}